// round 1
// baseline (speedup 1.0000x reference)
#include <cuda_runtime.h>
#include <cstdint>

// Problem constants
#define VCODES 8192
#define DDIM   256
#define MROWS  32768      // 8 * 16*16*16
#define SPAT   4096       // 16*16*16

// Output layout (concatenated f32)
#define O_QUANT 0ul
#define O_IDX   8388608ul
#define O_QD    8421376ul
#define O_NEWN  8421377ul
#define O_ZAVG  8429569ul
#define O_NEWW  10526721ul

// Scratch (no allocations allowed -> device globals)
__device__ unsigned long long g_best[MROWS];
__device__ float g_counts[VCODES];
__device__ float g_encsum[VCODES * DDIM];
__device__ float g_wsq[VCODES];
__device__ float g_wT[DDIM * VCODES];   // weight transposed [d][v]
__device__ float g_sumN;
__device__ float g_qd;

// ---------------------------------------------------------------------------
__global__ void k_zero() {
    int i = blockIdx.x * 256 + threadIdx.x;       // grid covers 2097152
    if (i < VCODES * DDIM) g_encsum[i] = 0.0f;
    if (i < MROWS)  g_best[i] = 0ull;
    if (i < VCODES) g_counts[i] = 0.0f;
    if (i == 0) { g_sumN = 0.0f; g_qd = 0.0f; }
}

// Transpose weight [V][D] -> wT [D][V]
__global__ void k_transpose(const float* __restrict__ w) {
    __shared__ float tile[32][33];
    int jb = blockIdx.x * 32;   // code dim
    int db = blockIdx.y * 32;   // feature dim
    int tx = threadIdx.x, ty = threadIdx.y;   // (32, 8)
#pragma unroll
    for (int i = 0; i < 4; ++i)
        tile[ty + i * 8][tx] = w[(size_t)(jb + ty + i * 8) * DDIM + db + tx];
    __syncthreads();
#pragma unroll
    for (int i = 0; i < 4; ++i)
        g_wT[(size_t)(db + ty + i * 8) * VCODES + jb + tx] = tile[tx][ty + i * 8];
}

// per-code squared norms + sum(N)
__global__ void k_wsq(const float* __restrict__ w, const float* __restrict__ N) {
    int gid  = blockIdx.x * 256 + threadIdx.x;   // grid 1024 -> 8192 warps
    int warp = gid >> 5, lane = gid & 31;
    const float* row = w + (size_t)warp * DDIM;
    float s = 0.0f;
#pragma unroll
    for (int t = lane; t < DDIM; t += 32) { float v = row[t]; s += v * v; }
#pragma unroll
    for (int o = 16; o; o >>= 1) s += __shfl_xor_sync(0xFFFFFFFFu, s, o);
    if (lane == 0) g_wsq[warp] = s;
    if (gid < VCODES) atomicAdd(&g_sumN, N[gid]);
}

// ---------------------------------------------------------------------------
// Fused SGEMM (scores = z . w) + per-row argmax of (score - 0.5*||w||^2)
// A = flat(x): flat[r][k] = x[b*1048576 + k*4096 + s], r = b*4096+s
// B = wT[k][j]
#define BM 128
#define BN 128
#define BK 16

__global__ __launch_bounds__(256, 2) void k_gemm(const float* __restrict__ x) {
    __shared__ float sm[2 * BK * BM];            // 16 KB (As | Bs)
    float* As = sm;
    float* Bs = sm + BK * BM;

    const int tid = threadIdx.x;
    const int tx = tid & 15;
    const int ty = tid >> 4;

    const int jbase = blockIdx.x * BN;
    const int rbase = blockIdx.y * BM;
    const int bb = rbase >> 12;          // batch (row tile never crosses batch)
    const int sb = rbase & 4095;
    const float* Abase = x + (size_t)bb * 1048576 + sb;

    float acc[8][8];
#pragma unroll
    for (int i = 0; i < 8; ++i)
#pragma unroll
        for (int j = 0; j < 8; ++j) acc[i][j] = 0.0f;

    float ra[8], rb[8];

    for (int k0 = 0; k0 < DDIM; k0 += BK) {
#pragma unroll
        for (int i = 0; i < 8; ++i) {
            int idx = tid + i * 256;                 // 0..2047
            int k = idx >> 7, m = idx & 127;
            ra[i] = Abase[(size_t)(k0 + k) * SPAT + m];
            rb[i] = g_wT[(size_t)(k0 + k) * VCODES + jbase + m];
        }
        __syncthreads();                             // prev compute done
#pragma unroll
        for (int i = 0; i < 8; ++i) {
            int idx = tid + i * 256;
            int k = idx >> 7, m = idx & 127;
            As[k * BM + m] = ra[i];
            Bs[k * BM + m] = rb[i];
        }
        __syncthreads();
#pragma unroll
        for (int k = 0; k < BK; ++k) {
            float4 a0 = *(const float4*)(As + k * BM + ty * 4);
            float4 a1 = *(const float4*)(As + k * BM + 64 + ty * 4);
            float4 b0 = *(const float4*)(Bs + k * BM + tx * 4);
            float4 b1 = *(const float4*)(Bs + k * BM + 64 + tx * 4);
            float av[8] = {a0.x, a0.y, a0.z, a0.w, a1.x, a1.y, a1.z, a1.w};
            float bv[8] = {b0.x, b0.y, b0.z, b0.w, b1.x, b1.y, b1.z, b1.w};
#pragma unroll
            for (int i = 0; i < 8; ++i)
#pragma unroll
                for (int j = 0; j < 8; ++j)
                    acc[i][j] += av[i] * bv[j];
        }
    }
    __syncthreads();   // done with As/Bs, reuse smem for reduction

    // epilogue: per-row argmax of acc - 0.5*wsq
    int   cg[8];
    float bias[8];
#pragma unroll
    for (int j = 0; j < 8; ++j) {
        cg[j]   = jbase + ((j < 4) ? (tx * 4 + j) : (64 + tx * 4 + j - 4));
        bias[j] = 0.5f * __ldg(&g_wsq[cg[j]]);
    }

    unsigned long long* red = (unsigned long long*)sm;   // 128*16*8B = 16KB
#pragma unroll
    for (int i = 0; i < 8; ++i) {
        int rl = (i < 4) ? (ty * 4 + i) : (64 + ty * 4 + i - 4);
        float bestv = acc[i][0] - bias[0];
        int   bestj = cg[0];
#pragma unroll
        for (int j = 1; j < 8; ++j) {
            float s = acc[i][j] - bias[j];
            if (s > bestv) { bestv = s; bestj = cg[j]; }   // cg ascending -> first-min tie-break
        }
        unsigned u = __float_as_uint(bestv);
        u = (u & 0x80000000u) ? ~u : (u | 0x80000000u);
        unsigned long long key =
            ((unsigned long long)u << 32) | (unsigned)(0xFFFFFFFFu - (unsigned)bestj);
        red[rl * 16 + tx] = key;
    }
    __syncthreads();
    if (tid < 128) {
        unsigned long long k = red[tid * 16];
#pragma unroll
        for (int t = 1; t < 16; ++t) {
            unsigned long long v = red[tid * 16 + t];
            if (v > k) k = v;
        }
        atomicMax(&g_best[rbase + tid], k);
    }
}

// ---------------------------------------------------------------------------
// Gather quant, write enc_idx, accumulate counts / enc_sum / quant_diff
__global__ void k_assign(const float* __restrict__ x, const float* __restrict__ w,
                         float* __restrict__ out) {
    int r = blockIdx.x * 256 + threadIdx.x;      // 32768 rows
    unsigned long long key = g_best[r];
    int idx = (int)(0xFFFFFFFFu - (unsigned)(key & 0xFFFFFFFFull));
    int b = r >> 12, s = r & 4095;
    const float* wrow = w + (size_t)idx * DDIM;
    float* encrow = g_encsum + (size_t)idx * DDIM;
    size_t xo = (size_t)b * 1048576 + s;
    float qd = 0.0f;
#pragma unroll 4
    for (int d = 0; d < DDIM; ++d) {
        float wv = __ldg(wrow + d);
        float xv = x[xo + (size_t)d * SPAT];
        out[O_QUANT + xo + (size_t)d * SPAT] = (wv - xv) + xv;  // mimic (q-x)+x
        float df = xv - wv;
        qd += df * df;
        atomicAdd(encrow + d, xv);
    }
    out[O_IDX + r] = (float)idx;
    atomicAdd(&g_counts[idx], 1.0f);
    atomicAdd(&g_qd, qd);
}

// ---------------------------------------------------------------------------
// EMA update + final outputs
__global__ void k_update(const float* __restrict__ N, const float* __restrict__ z_avg,
                         float* __restrict__ out) {
    int i = blockIdx.x * 256 + threadIdx.x;      // covers V*D = 2097152
    if (i >= VCODES * DDIM) return;
    int v = i >> 8, d = i & 255;
    float gamma = 0.99f, om = 0.01f, eps = 1e-7f;
    float n  = gamma * g_sumN + om * (float)MROWS;   // sum(new_N)
    float nN = gamma * N[v] + om * g_counts[v];
    float wgt = (nN + eps) / (n + (float)VCODES * eps) * n;
    float za = gamma * z_avg[i] + om * g_encsum[i];
    out[O_ZAVG + i] = za;
    out[O_NEWW + i] = za / wgt;
    if (d == 0) out[O_NEWN + v] = nN;
    if (i == 0) out[O_QD] = g_qd * (1.0f / 8388608.0f);
}

// ---------------------------------------------------------------------------
extern "C" void kernel_launch(void* const* d_in, const int* in_sizes, int n_in,
                              void* d_out, int out_size) {
    const float* x    = (const float*)d_in[0];
    const float* w    = (const float*)d_in[1];
    const float* N    = (const float*)d_in[2];
    const float* zavg = (const float*)d_in[3];
    float* out = (float*)d_out;

    k_zero<<<8192, 256>>>();
    k_transpose<<<dim3(256, 8), dim3(32, 8)>>>(w);
    k_wsq<<<1024, 256>>>(w, N);
    k_gemm<<<dim3(VCODES / BN, MROWS / BM), 256>>>(x);
    k_assign<<<MROWS / 256, 256>>>(x, w, out);
    k_update<<<VCODES * DDIM / 256, 256>>>(N, zavg, out);
}

// round 3
// speedup vs baseline: 2.8475x; 2.8475x over previous
#include <cuda_runtime.h>
#include <cuda_bf16.h>
#include <cstdint>

// Problem constants
#define VCODES 8192
#define DDIM   256
#define MROWS  32768      // 8 * 16*16*16
#define SPAT   4096       // 16*16*16

// Output layout (concatenated f32)
#define O_QUANT 0ul
#define O_IDX   8388608ul
#define O_QD    8421376ul
#define O_NEWN  8421377ul
#define O_ZAVG  8429569ul
#define O_NEWW  10526721ul

#define MARGIN 3.0f

// ---------------------------------------------------------------------------
// Scratch (device globals; no allocations allowed)
__device__ unsigned long long g_best[MROWS];
__device__ int   g_idx[MROWS];
__device__ float g_counts[VCODES];
__device__ float g_encsum[VCODES * DDIM];
__device__ float g_wsq[VCODES];
__device__ float g_sumN;
__device__ float g_qd;
__device__ __nv_bfloat16 g_abf[MROWS * DDIM];    // flat x, bf16
__device__ __nv_bfloat16 g_wbf[VCODES * DDIM];   // weight, bf16
__device__ __nv_bfloat16 g_scores[(size_t)MROWS * VCODES];  // coarse scores

// ---------------------------------------------------------------------------
__device__ __forceinline__ uint32_t smem_u32(const void* p) {
    uint32_t a;
    asm("{ .reg .u64 t; cvta.to.shared.u64 t, %1; cvt.u32.u64 %0, t; }" : "=r"(a) : "l"(p));
    return a;
}
__device__ __forceinline__ void cp16(uint32_t dst, const void* src) {
    asm volatile("cp.async.cg.shared.global [%0], [%1], 16;" :: "r"(dst), "l"(src) : "memory");
}
__device__ __forceinline__ void ldm4(uint32_t* r, uint32_t addr) {
    asm volatile("ldmatrix.sync.aligned.m8n8.x4.shared.b16 {%0,%1,%2,%3}, [%4];"
                 : "=r"(r[0]), "=r"(r[1]), "=r"(r[2]), "=r"(r[3]) : "r"(addr));
}
__device__ __forceinline__ void mma16816(float* c, const uint32_t* a, const uint32_t* b) {
    asm volatile(
        "mma.sync.aligned.m16n8k16.row.col.f32.bf16.bf16.f32 "
        "{%0,%1,%2,%3}, {%4,%5,%6,%7}, {%8,%9}, {%0,%1,%2,%3};"
        : "+f"(c[0]), "+f"(c[1]), "+f"(c[2]), "+f"(c[3])
        : "r"(a[0]), "r"(a[1]), "r"(a[2]), "r"(a[3]), "r"(b[0]), "r"(b[1]));
}

// ---------------------------------------------------------------------------
__global__ void k_zero() {
    int i = blockIdx.x * 256 + threadIdx.x;       // grid covers 2097152
    if (i < VCODES * DDIM) g_encsum[i] = 0.0f;
    if (i < MROWS)  g_best[i] = 0ull;
    if (i < VCODES) g_counts[i] = 0.0f;
    if (i == 0) { g_sumN = 0.0f; g_qd = 0.0f; }
}

// x (b, D=k, s) -> g_abf[r=b*4096+s][k] bf16
__global__ void k_prep_x(const float* __restrict__ x) {
    __shared__ float t[32][33];
    int k0 = blockIdx.x * 32, s0 = blockIdx.y * 32, b = blockIdx.z;
    int tx = threadIdx.x, ty = threadIdx.y;       // (32, 8)
#pragma unroll
    for (int i = 0; i < 4; ++i)
        t[ty + i * 8][tx] = x[(size_t)b * 1048576 + (size_t)(k0 + ty + i * 8) * SPAT + s0 + tx];
    __syncthreads();
#pragma unroll
    for (int i = 0; i < 4; ++i) {
        int r = b * SPAT + s0 + ty + i * 8;
        g_abf[(size_t)r * DDIM + k0 + tx] = __float2bfloat16(t[tx][ty + i * 8]);
    }
}

// weight -> bf16; wsq per code; sum(N)
__global__ void k_prep_w(const float* __restrict__ w, const float* __restrict__ N) {
    int gid  = blockIdx.x * 256 + threadIdx.x;
    int v = gid >> 5, lane = gid & 31;
    const float* row = w + (size_t)v * DDIM;
    float s = 0.0f;
#pragma unroll
    for (int t = lane; t < DDIM; t += 32) {
        float a = row[t];
        s += a * a;
        g_wbf[(size_t)v * DDIM + t] = __float2bfloat16(a);
    }
#pragma unroll
    for (int o = 16; o; o >>= 1) s += __shfl_xor_sync(0xFFFFFFFFu, s, o);
    if (lane == 0) {
        g_wsq[v] = s;
        atomicAdd(&g_sumN, N[v]);
    }
}

// ---------------------------------------------------------------------------
// bf16 mma.sync GEMM: C[128m x 128n] = A(flat x) . B(weight)^T per CTA,
// fused coarse-score store + per-row argmax atomicMax.
// SMEM rows stride 80B (conflict-free ldmatrix), 2-stage cp.async pipeline.
__global__ __launch_bounds__(256) void k_gemm() {
    __shared__ __align__(16) char sm[2 * 20480];
    const int tid = threadIdx.x;
    const int lane = tid & 31, wid = tid >> 5;
    const int wm = wid & 1, wn = wid >> 1;        // warp tile 64m x 32n, 2x4 warps
    const int jbase = blockIdx.x * 128;
    const int rbase = blockIdx.y * 128;
    const uint32_t smb = smem_u32(sm);

    const int sel = lane >> 3, rin = lane & 7;
    uint32_t offA[4], offB[2];
#pragma unroll
    for (int i = 0; i < 4; ++i)
        offA[i] = (uint32_t)((wm * 64 + i * 16 + rin + ((sel & 1) << 3)) * 80 + ((sel >> 1) << 4));
#pragma unroll
    for (int p = 0; p < 2; ++p)
        offB[p] = (uint32_t)(10240 + (wn * 32 + p * 16 + rin + ((sel >> 1) << 3)) * 80 + ((sel & 1) << 4));

    float acc[4][4][4];
#pragma unroll
    for (int i = 0; i < 4; ++i)
#pragma unroll
        for (int j = 0; j < 4; ++j)
#pragma unroll
            for (int q = 0; q < 4; ++q) acc[i][j][q] = 0.0f;

    const int rw0 = tid >> 2, cc = tid & 3;

#define LOAD_STAGE(c, st)                                                               \
    do {                                                                                \
        uint32_t sb_ = smb + (st) * 20480;                                              \
        int k0_ = (c) * 32;                                                             \
        cp16(sb_ + rw0 * 80 + cc * 16,                                                  \
             g_abf + (size_t)(rbase + rw0) * DDIM + k0_ + cc * 8);                      \
        cp16(sb_ + 10240 + rw0 * 80 + cc * 16,                                          \
             g_wbf + (size_t)(jbase + rw0) * DDIM + k0_ + cc * 8);                      \
        cp16(sb_ + (rw0 + 64) * 80 + cc * 16,                                           \
             g_abf + (size_t)(rbase + rw0 + 64) * DDIM + k0_ + cc * 8);                 \
        cp16(sb_ + 10240 + (rw0 + 64) * 80 + cc * 16,                                   \
             g_wbf + (size_t)(jbase + rw0 + 64) * DDIM + k0_ + cc * 8);                 \
        asm volatile("cp.async.commit_group;" ::: "memory");                            \
    } while (0)

    LOAD_STAGE(0, 0);
#pragma unroll 1
    for (int c = 0; c < 8; ++c) {
        if (c < 7) {
            LOAD_STAGE(c + 1, (c + 1) & 1);
            asm volatile("cp.async.wait_group 1;" ::: "memory");
        } else {
            asm volatile("cp.async.wait_group 0;" ::: "memory");
        }
        __syncthreads();
        uint32_t sb = smb + (c & 1) * 20480;
#pragma unroll
        for (int ks = 0; ks < 2; ++ks) {
            uint32_t a[4][4], bf[4][2];
#pragma unroll
            for (int i = 0; i < 4; ++i) ldm4(a[i], sb + offA[i] + ks * 32);
#pragma unroll
            for (int p = 0; p < 2; ++p) {
                uint32_t r4[4];
                ldm4(r4, sb + offB[p] + ks * 32);
                bf[2 * p][0] = r4[0]; bf[2 * p][1] = r4[1];
                bf[2 * p + 1][0] = r4[2]; bf[2 * p + 1][1] = r4[3];
            }
#pragma unroll
            for (int i = 0; i < 4; ++i)
#pragma unroll
                for (int j = 0; j < 4; ++j)
                    mma16816(acc[i][j], a[i], bf[j]);
        }
        __syncthreads();
    }
#undef LOAD_STAGE

    // epilogue: scores = acc - 0.5*wsq; store bf16; per-row argmax
    const int lq = lane >> 2, lr = lane & 3;
    unsigned long long key[8];
    float bv[8]; int bj[8];
#pragma unroll
    for (int s = 0; s < 8; ++s) { bv[s] = -3.4e38f; bj[s] = 0; }

#pragma unroll
    for (int j = 0; j < 4; ++j) {
        int col = jbase + wn * 32 + j * 8 + lr * 2;
        float2 wq = *reinterpret_cast<const float2*>(&g_wsq[col]);
#pragma unroll
        for (int i = 0; i < 4; ++i) {
#pragma unroll
            for (int h = 0; h < 2; ++h) {
                float s0 = acc[i][j][h * 2 + 0] - 0.5f * wq.x;
                float s1 = acc[i][j][h * 2 + 1] - 0.5f * wq.y;
                int grow = rbase + wm * 64 + i * 16 + lq + h * 8;
                __nv_bfloat162 pr = __floats2bfloat162_rn(s0, s1);
                *reinterpret_cast<__nv_bfloat162*>(
                    &g_scores[(size_t)grow * VCODES + col]) = pr;
                int slot = i * 2 + h;
                if (s0 > bv[slot]) { bv[slot] = s0; bj[slot] = col; }
                if (s1 > bv[slot]) { bv[slot] = s1; bj[slot] = col + 1; }
            }
        }
    }
#pragma unroll
    for (int s = 0; s < 8; ++s) {
        unsigned u = __float_as_uint(bv[s]);
        u = (u & 0x80000000u) ? ~u : (u | 0x80000000u);
        key[s] = ((unsigned long long)u << 32) |
                 (unsigned)(0xFFFFFFFFu - (unsigned)bj[s]);
#pragma unroll
        for (int o = 1; o < 4; o <<= 1) {
            unsigned long long v = __shfl_xor_sync(0xFFFFFFFFu, key[s], o);
            if (v > key[s]) key[s] = v;
        }
        if (lr == 0) {
            int grow = rbase + wm * 64 + (s >> 1) * 16 + lq + (s & 1) * 8;
            atomicMax(&g_best[grow], key[s]);
        }
    }
}

// ---------------------------------------------------------------------------
// Repair: per-row warp rescans bf16 scores, exact fp32 recompute of candidates.
__global__ void k_repair(const float* __restrict__ x, const float* __restrict__ w,
                         float* __restrict__ out) {
    int r = blockIdx.x * 8 + (threadIdx.x >> 5);
    int lane = threadIdx.x & 31;
    unsigned long long kk = g_best[r];
    unsigned u = (unsigned)(kk >> 32);
    unsigned bits = (u & 0x80000000u) ? (u & 0x7FFFFFFFu) : ~u;
    float thr = __uint_as_float(bits) - MARGIN;
    int b = r >> 12, s = r & 4095;
    const float* xb = x + (size_t)b * 1048576 + s;
    float bestv = -3.4e38f;
    int   bestj = 0;
    const uint4* rowp = reinterpret_cast<const uint4*>(g_scores + (size_t)r * VCODES);
#pragma unroll 1
    for (int it = 0; it < 32; ++it) {
        uint4 v = rowp[it * 32 + lane];
        unsigned m = 0;
        unsigned wds[4] = {v.x, v.y, v.z, v.w};
#pragma unroll
        for (int q = 0; q < 4; ++q) {
            __nv_bfloat162 h2 = *reinterpret_cast<__nv_bfloat162*>(&wds[q]);
            float2 f = __bfloat1622float2(h2);
            if (f.x >= thr) m |= 1u << (2 * q);
            if (f.y >= thr) m |= 1u << (2 * q + 1);
        }
        unsigned act = __ballot_sync(0xFFFFFFFFu, m != 0);
        while (act) {
            int src = __ffs(act) - 1; act &= act - 1;
            unsigned mm = __shfl_sync(0xFFFFFFFFu, m, src);
            while (mm) {
                int bit = __ffs(mm) - 1; mm &= mm - 1;
                int j = it * 256 + src * 8 + bit;
                const float* wr = w + (size_t)j * DDIM;
                float p = 0.0f;
#pragma unroll
                for (int q = 0; q < 8; ++q) {
                    int k = lane + q * 32;
                    p += xb[(size_t)k * SPAT] * wr[k];
                }
#pragma unroll
                for (int o = 16; o; o >>= 1) p += __shfl_xor_sync(0xFFFFFFFFu, p, o);
                float sc = p - 0.5f * g_wsq[j];
                if (sc > bestv) { bestv = sc; bestj = j; }   // ascending j -> first-idx tie-break
            }
        }
    }
    if (lane == 0) {
        g_idx[r] = bestj;
        out[O_IDX + r] = (float)bestj;
        atomicAdd(&g_counts[bestj], 1.0f);
    }
}

// ---------------------------------------------------------------------------
// quant write (coalesced over spatial), enc_sum atomics, quant_diff
__global__ void k_assign(const float* __restrict__ x, const float* __restrict__ w,
                         float* __restrict__ out) {
    __shared__ int sidx[128];
    __shared__ float red[8];
    int bi = blockIdx.x;
    int b = bi >> 5, s0 = (bi & 31) * 128;
    int tid = threadIdx.x, ts = tid & 127, dg = tid >> 7;
    if (tid < 128) sidx[tid] = g_idx[b * SPAT + s0 + tid];
    __syncthreads();
    int j = sidx[ts];
    const float* wr = w + (size_t)j * DDIM;
    float* er = g_encsum + (size_t)j * DDIM;
    size_t basex = (size_t)b * 1048576 + s0 + ts;
    float qd = 0.0f;
#pragma unroll 4
    for (int d = dg; d < 256; d += 2) {
        size_t off = basex + (size_t)d * SPAT;
        float xv = x[off];
        float wv = __ldg(wr + d);
        out[O_QUANT + off] = (wv - xv) + xv;
        float df = xv - wv;
        qd += df * df;
        atomicAdd(er + d, xv);
    }
#pragma unroll
    for (int o = 16; o; o >>= 1) qd += __shfl_xor_sync(0xFFFFFFFFu, qd, o);
    if ((tid & 31) == 0) red[tid >> 5] = qd;
    __syncthreads();
    if (tid == 0) {
        float t = 0.0f;
#pragma unroll
        for (int i = 0; i < 8; ++i) t += red[i];
        atomicAdd(&g_qd, t);
    }
}

// ---------------------------------------------------------------------------
__global__ void k_update(const float* __restrict__ N, const float* __restrict__ z_avg,
                         float* __restrict__ out) {
    int i = blockIdx.x * 256 + threadIdx.x;
    if (i >= VCODES * DDIM) return;
    int v = i >> 8, d = i & 255;
    float gamma = 0.99f, om = 0.01f, eps = 1e-7f;
    float n  = gamma * g_sumN + om * (float)MROWS;
    float nN = gamma * N[v] + om * g_counts[v];
    float wgt = (nN + eps) / (n + (float)VCODES * eps) * n;
    float za = gamma * z_avg[i] + om * g_encsum[i];
    out[O_ZAVG + i] = za;
    out[O_NEWW + i] = za / wgt;
    if (d == 0) out[O_NEWN + v] = nN;
    if (i == 0) out[O_QD] = g_qd * (1.0f / 8388608.0f);
}

// ---------------------------------------------------------------------------
extern "C" void kernel_launch(void* const* d_in, const int* in_sizes, int n_in,
                              void* d_out, int out_size) {
    const float* x    = (const float*)d_in[0];
    const float* w    = (const float*)d_in[1];
    const float* N    = (const float*)d_in[2];
    const float* zavg = (const float*)d_in[3];
    float* out = (float*)d_out;

    k_zero<<<8192, 256>>>();
    k_prep_x<<<dim3(8, 128, 8), dim3(32, 8)>>>(x);
    k_prep_w<<<1024, 256>>>(w, N);
    k_gemm<<<dim3(VCODES / 128, MROWS / 128), 256>>>();
    k_repair<<<MROWS / 8, 256>>>(x, w, out);
    k_assign<<<256, 256>>>(x, w, out);
    k_update<<<VCODES * DDIM / 256, 256>>>(N, zavg, out);
}

// round 5
// speedup vs baseline: 3.2192x; 1.1306x over previous
#include <cuda_runtime.h>
#include <cuda_bf16.h>
#include <cstdint>

// Problem constants
#define VCODES 8192
#define DDIM   256
#define MROWS  32768      // 8 * 16*16*16
#define SPAT   4096       // 16*16*16

// Output layout (concatenated f32)
#define O_QUANT 0ul
#define O_IDX   8388608ul
#define O_QD    8421376ul
#define O_NEWN  8421377ul
#define O_ZAVG  8429569ul
#define O_NEWW  10526721ul

#define MARGIN 3.0f

// ---------------------------------------------------------------------------
// Scratch (device globals; no allocations allowed)
__device__ unsigned long long g_best[MROWS];
__device__ int   g_idx[MROWS];
__device__ float g_counts[VCODES];
__device__ float g_encsum[VCODES * DDIM];
__device__ float g_wsq[VCODES];
__device__ float g_sumN;
__device__ float g_qd;
__device__ __nv_bfloat16 g_abf[MROWS * DDIM];    // flat x, bf16
__device__ __nv_bfloat16 g_wbf[VCODES * DDIM];   // weight, bf16
__device__ __nv_bfloat16 g_scores[(size_t)MROWS * VCODES];  // coarse scores

// ---------------------------------------------------------------------------
__device__ __forceinline__ uint32_t smem_u32(const void* p) {
    uint32_t a;
    asm("{ .reg .u64 t; cvta.to.shared.u64 t, %1; cvt.u32.u64 %0, t; }" : "=r"(a) : "l"(p));
    return a;
}
__device__ __forceinline__ void cp16(uint32_t dst, const void* src) {
    asm volatile("cp.async.cg.shared.global [%0], [%1], 16;" :: "r"(dst), "l"(src) : "memory");
}
__device__ __forceinline__ void ldm4(uint32_t* r, uint32_t addr) {
    asm volatile("ldmatrix.sync.aligned.m8n8.x4.shared.b16 {%0,%1,%2,%3}, [%4];"
                 : "=r"(r[0]), "=r"(r[1]), "=r"(r[2]), "=r"(r[3]) : "r"(addr));
}
__device__ __forceinline__ void mma16816(float* c, const uint32_t* a, const uint32_t* b) {
    asm volatile(
        "mma.sync.aligned.m16n8k16.row.col.f32.bf16.bf16.f32 "
        "{%0,%1,%2,%3}, {%4,%5,%6,%7}, {%8,%9}, {%0,%1,%2,%3};"
        : "+f"(c[0]), "+f"(c[1]), "+f"(c[2]), "+f"(c[3])
        : "r"(a[0]), "r"(a[1]), "r"(a[2]), "r"(a[3]), "r"(b[0]), "r"(b[1]));
}

// ---------------------------------------------------------------------------
__global__ void k_zero() {
    int i = blockIdx.x * 256 + threadIdx.x;       // grid covers 2097152
    if (i < VCODES * DDIM) g_encsum[i] = 0.0f;
    if (i < MROWS)  g_best[i] = 0ull;
    if (i < VCODES) g_counts[i] = 0.0f;
    if (i == 0) { g_sumN = 0.0f; g_qd = 0.0f; }
}

// x (b, D=k, s) -> g_abf[r=b*4096+s][k] bf16
__global__ void k_prep_x(const float* __restrict__ x) {
    __shared__ float t[32][33];
    int k0 = blockIdx.x * 32, s0 = blockIdx.y * 32, b = blockIdx.z;
    int tx = threadIdx.x, ty = threadIdx.y;       // (32, 8)
#pragma unroll
    for (int i = 0; i < 4; ++i)
        t[ty + i * 8][tx] = x[(size_t)b * 1048576 + (size_t)(k0 + ty + i * 8) * SPAT + s0 + tx];
    __syncthreads();
#pragma unroll
    for (int i = 0; i < 4; ++i) {
        int r = b * SPAT + s0 + ty + i * 8;
        g_abf[(size_t)r * DDIM + k0 + tx] = __float2bfloat16(t[tx][ty + i * 8]);
    }
}

// weight -> bf16; wsq per code; sum(N)
__global__ void k_prep_w(const float* __restrict__ w, const float* __restrict__ N) {
    int gid  = blockIdx.x * 256 + threadIdx.x;
    int v = gid >> 5, lane = gid & 31;
    const float* row = w + (size_t)v * DDIM;
    float s = 0.0f;
#pragma unroll
    for (int t = lane; t < DDIM; t += 32) {
        float a = row[t];
        s += a * a;
        g_wbf[(size_t)v * DDIM + t] = __float2bfloat16(a);
    }
#pragma unroll
    for (int o = 16; o; o >>= 1) s += __shfl_xor_sync(0xFFFFFFFFu, s, o);
    if (lane == 0) {
        g_wsq[v] = s;
        atomicAdd(&g_sumN, N[v]);
    }
}

// ---------------------------------------------------------------------------
// bf16 mma.sync GEMM: C[128m x 128n] per CTA, 3-stage cp.async pipeline,
// 64B rows with XOR swizzle (chunk ^= (row>>1)&3) -> conflict-free ldmatrix.
// Stage = A 128x64B (8KB) + B 128x64B (8KB) = 16KB; 3 stages = 48KB static.
__global__ __launch_bounds__(256, 2) void k_gemm() {
    __shared__ __align__(16) char sm[49152];
    const int tid = threadIdx.x;
    const int lane = tid & 31, wid = tid >> 5;
    const int wm = wid & 1, wn = wid >> 1;        // warp tile 64m x 32n
    const int jbase = blockIdx.x * 128;
    const int rbase = blockIdx.y * 128;
    const uint32_t smb = smem_u32(sm);

    const int sel = lane >> 3, rin = lane & 7;

    // ldmatrix fragment offsets (per kstep, XOR-swizzled)
    uint32_t offA[4][2], offB[2][2];
#pragma unroll
    for (int i = 0; i < 4; ++i) {
        int row = wm * 64 + i * 16 + rin + ((sel & 1) << 3);
        int h = sel >> 1, v = (row >> 1) & 3;
#pragma unroll
        for (int ks = 0; ks < 2; ++ks)
            offA[i][ks] = (uint32_t)(row * 64 + (((ks * 2 + h) ^ v) << 4));
    }
#pragma unroll
    for (int p = 0; p < 2; ++p) {
        int row = wn * 32 + p * 16 + rin + ((sel >> 1) << 3);
        int h = sel & 1, v = (row >> 1) & 3;
#pragma unroll
        for (int ks = 0; ks < 2; ++ks)
            offB[p][ks] = (uint32_t)(8192 + row * 64 + (((ks * 2 + h) ^ v) << 4));
    }

    // cp.async store offsets / source pointers
    const int rw = tid >> 2, cc = tid & 3;
    const uint32_t dA0 = (uint32_t)(rw * 64 + ((cc ^ ((rw >> 1) & 3)) << 4));
    const uint32_t dA1 = (uint32_t)((rw + 64) * 64 + ((cc ^ (((rw + 64) >> 1) & 3)) << 4));
    const uint32_t dB0 = 8192 + dA0;
    const uint32_t dB1 = 8192 + dA1;
    const __nv_bfloat16* sA0 = g_abf + (size_t)(rbase + rw) * DDIM + cc * 8;
    const __nv_bfloat16* sA1 = sA0 + (size_t)64 * DDIM;
    const __nv_bfloat16* sB0 = g_wbf + (size_t)(jbase + rw) * DDIM + cc * 8;
    const __nv_bfloat16* sB1 = sB0 + (size_t)64 * DDIM;

    float acc[4][4][4];
#pragma unroll
    for (int i = 0; i < 4; ++i)
#pragma unroll
        for (int j = 0; j < 4; ++j)
#pragma unroll
            for (int q = 0; q < 4; ++q) acc[i][j][q] = 0.0f;

#define LOAD_STAGE(st, ko)                                                \
    do {                                                                  \
        uint32_t sb_ = smb + (st) * 16384;                                \
        cp16(sb_ + dA0, sA0 + (ko)); cp16(sb_ + dA1, sA1 + (ko));         \
        cp16(sb_ + dB0, sB0 + (ko)); cp16(sb_ + dB1, sB1 + (ko));         \
        asm volatile("cp.async.commit_group;" ::: "memory");              \
    } while (0)

    LOAD_STAGE(0, 0);
    LOAD_STAGE(1, 32);

#pragma unroll 1
    for (int c = 0; c < 8; ++c) {
        if (c < 7) asm volatile("cp.async.wait_group 1;" ::: "memory");
        else       asm volatile("cp.async.wait_group 0;" ::: "memory");
        __syncthreads();
        if (c < 6) {
            int st = c + 2;                       // chunk index of prefetch
            st -= (st >= 6) ? 6 : ((st >= 3) ? 3 : 0);   // proper mod 3
            LOAD_STAGE(st, (c + 2) * 32);
        }
        int cs = c;
        cs -= (cs >= 6) ? 6 : ((cs >= 3) ? 3 : 0);
        uint32_t sb = smb + cs * 16384;
#pragma unroll
        for (int ks = 0; ks < 2; ++ks) {
            uint32_t a[4][4], bf[4][2];
#pragma unroll
            for (int i = 0; i < 4; ++i) ldm4(a[i], sb + offA[i][ks]);
#pragma unroll
            for (int p = 0; p < 2; ++p) {
                uint32_t r4[4];
                ldm4(r4, sb + offB[p][ks]);
                bf[2 * p][0] = r4[0]; bf[2 * p][1] = r4[1];
                bf[2 * p + 1][0] = r4[2]; bf[2 * p + 1][1] = r4[3];
            }
#pragma unroll
            for (int i = 0; i < 4; ++i)
#pragma unroll
                for (int j = 0; j < 4; ++j)
                    mma16816(acc[i][j], a[i], bf[j]);
        }
    }
#undef LOAD_STAGE

    // epilogue: scores = acc - 0.5*wsq; store bf16; per-row argmax
    const int lq = lane >> 2, lr = lane & 3;
    float bv[8]; int bj[8];
#pragma unroll
    for (int s = 0; s < 8; ++s) { bv[s] = -3.4e38f; bj[s] = 0; }

#pragma unroll
    for (int j = 0; j < 4; ++j) {
        int col = jbase + wn * 32 + j * 8 + lr * 2;
        float2 wq = *reinterpret_cast<const float2*>(&g_wsq[col]);
#pragma unroll
        for (int i = 0; i < 4; ++i) {
#pragma unroll
            for (int h = 0; h < 2; ++h) {
                float s0 = acc[i][j][h * 2 + 0] - 0.5f * wq.x;
                float s1 = acc[i][j][h * 2 + 1] - 0.5f * wq.y;
                int grow = rbase + wm * 64 + i * 16 + lq + h * 8;
                __nv_bfloat162 pr = __floats2bfloat162_rn(s0, s1);
                *reinterpret_cast<__nv_bfloat162*>(
                    &g_scores[(size_t)grow * VCODES + col]) = pr;
                int slot = i * 2 + h;
                if (s0 > bv[slot]) { bv[slot] = s0; bj[slot] = col; }
                if (s1 > bv[slot]) { bv[slot] = s1; bj[slot] = col + 1; }
            }
        }
    }
#pragma unroll
    for (int s = 0; s < 8; ++s) {
        unsigned u = __float_as_uint(bv[s]);
        u = (u & 0x80000000u) ? ~u : (u | 0x80000000u);
        unsigned long long key = ((unsigned long long)u << 32) |
                                 (unsigned)(0xFFFFFFFFu - (unsigned)bj[s]);
#pragma unroll
        for (int o = 1; o < 4; o <<= 1) {
            unsigned long long v = __shfl_xor_sync(0xFFFFFFFFu, key, o);
            if (v > key) key = v;
        }
        if (lr == 0) {
            int grow = rbase + wm * 64 + (s >> 1) * 16 + lq + (s & 1) * 8;
            atomicMax(&g_best[grow], key);
        }
    }
}

// ---------------------------------------------------------------------------
// Repair: per-row warp rescans bf16 scores, exact fp32 recompute of candidates.
__global__ void k_repair(const float* __restrict__ x, const float* __restrict__ w,
                         float* __restrict__ out) {
    int r = blockIdx.x * 8 + (threadIdx.x >> 5);
    int lane = threadIdx.x & 31;
    unsigned long long kk = g_best[r];
    unsigned u = (unsigned)(kk >> 32);
    unsigned bits = (u & 0x80000000u) ? (u & 0x7FFFFFFFu) : ~u;
    float thr = __uint_as_float(bits) - MARGIN;
    int b = r >> 12, s = r & 4095;
    const float* xb = x + (size_t)b * 1048576 + s;
    float bestv = -3.4e38f;
    int   bestj = 0;
    const uint4* rowp = reinterpret_cast<const uint4*>(g_scores + (size_t)r * VCODES);
#pragma unroll 1
    for (int it = 0; it < 32; ++it) {
        uint4 v = rowp[it * 32 + lane];
        unsigned m = 0;
        unsigned wds[4] = {v.x, v.y, v.z, v.w};
#pragma unroll
        for (int q = 0; q < 4; ++q) {
            __nv_bfloat162 h2 = *reinterpret_cast<__nv_bfloat162*>(&wds[q]);
            float2 f = __bfloat1622float2(h2);
            if (f.x >= thr) m |= 1u << (2 * q);
            if (f.y >= thr) m |= 1u << (2 * q + 1);
        }
        unsigned act = __ballot_sync(0xFFFFFFFFu, m != 0);
        while (act) {
            int src = __ffs(act) - 1; act &= act - 1;
            unsigned mm = __shfl_sync(0xFFFFFFFFu, m, src);
            while (mm) {
                int bit = __ffs(mm) - 1; mm &= mm - 1;
                int j = it * 256 + src * 8 + bit;
                const float* wr = w + (size_t)j * DDIM;
                float p = 0.0f;
#pragma unroll
                for (int q = 0; q < 8; ++q) {
                    int k = lane + q * 32;
                    p += xb[(size_t)k * SPAT] * wr[k];
                }
#pragma unroll
                for (int o = 16; o; o >>= 1) p += __shfl_xor_sync(0xFFFFFFFFu, p, o);
                float sc = p - 0.5f * g_wsq[j];
                if (sc > bestv) { bestv = sc; bestj = j; }   // ascending j -> first-idx tie-break
            }
        }
    }
    if (lane == 0) {
        g_idx[r] = bestj;
        out[O_IDX + r] = (float)bestj;
        atomicAdd(&g_counts[bestj], 1.0f);
    }
}

// ---------------------------------------------------------------------------
// quant write (coalesced over spatial), enc_sum atomics, quant_diff
__global__ void k_assign(const float* __restrict__ x, const float* __restrict__ w,
                         float* __restrict__ out) {
    __shared__ int sidx[128];
    __shared__ float red[8];
    int bi = blockIdx.x;
    int b = bi >> 5, s0 = (bi & 31) * 128;
    int tid = threadIdx.x, ts = tid & 127, dg = tid >> 7;
    if (tid < 128) sidx[tid] = g_idx[b * SPAT + s0 + tid];
    __syncthreads();
    int j = sidx[ts];
    const float* wr = w + (size_t)j * DDIM;
    float* er = g_encsum + (size_t)j * DDIM;
    size_t basex = (size_t)b * 1048576 + s0 + ts;
    float qd = 0.0f;
#pragma unroll 4
    for (int d = dg; d < 256; d += 2) {
        size_t off = basex + (size_t)d * SPAT;
        float xv = x[off];
        float wv = __ldg(wr + d);
        out[O_QUANT + off] = (wv - xv) + xv;
        float df = xv - wv;
        qd += df * df;
        atomicAdd(er + d, xv);
    }
#pragma unroll
    for (int o = 16; o; o >>= 1) qd += __shfl_xor_sync(0xFFFFFFFFu, qd, o);
    if ((tid & 31) == 0) red[tid >> 5] = qd;
    __syncthreads();
    if (tid == 0) {
        float t = 0.0f;
#pragma unroll
        for (int i = 0; i < 8; ++i) t += red[i];
        atomicAdd(&g_qd, t);
    }
}

// ---------------------------------------------------------------------------
__global__ void k_update(const float* __restrict__ N, const float* __restrict__ z_avg,
                         float* __restrict__ out) {
    int i = blockIdx.x * 256 + threadIdx.x;
    if (i >= VCODES * DDIM) return;
    int v = i >> 8, d = i & 255;
    float gamma = 0.99f, om = 0.01f, eps = 1e-7f;
    float n  = gamma * g_sumN + om * (float)MROWS;
    float nN = gamma * N[v] + om * g_counts[v];
    float wgt = (nN + eps) / (n + (float)VCODES * eps) * n;
    float za = gamma * z_avg[i] + om * g_encsum[i];
    out[O_ZAVG + i] = za;
    out[O_NEWW + i] = za / wgt;
    if (d == 0) out[O_NEWN + v] = nN;
    if (i == 0) out[O_QD] = g_qd * (1.0f / 8388608.0f);
}

// ---------------------------------------------------------------------------
extern "C" void kernel_launch(void* const* d_in, const int* in_sizes, int n_in,
                              void* d_out, int out_size) {
    const float* x    = (const float*)d_in[0];
    const float* w    = (const float*)d_in[1];
    const float* N    = (const float*)d_in[2];
    const float* zavg = (const float*)d_in[3];
    float* out = (float*)d_out;

    k_zero<<<8192, 256>>>();
    k_prep_x<<<dim3(8, 128, 8), dim3(32, 8)>>>(x);
    k_prep_w<<<1024, 256>>>(w, N);
    k_gemm<<<dim3(VCODES / 128, MROWS / 128), 256>>>();
    k_repair<<<MROWS / 8, 256>>>(x, w, out);
    k_assign<<<256, 256>>>(x, w, out);
    k_update<<<VCODES * DDIM / 256, 256>>>(N, zavg, out);
}

// round 6
// speedup vs baseline: 3.4604x; 1.0749x over previous
#include <cuda_runtime.h>
#include <cuda_bf16.h>
#include <cstdint>

// Problem constants
#define VCODES 8192
#define DDIM   256
#define MROWS  32768      // 8 * 16*16*16
#define SPAT   4096       // 16*16*16

// Output layout (concatenated f32)
#define O_QUANT 0ul
#define O_IDX   8388608ul
#define O_QD    8421376ul
#define O_NEWN  8421377ul
#define O_ZAVG  8429569ul
#define O_NEWW  10526721ul

#define MARGIN 3.0f

// ---------------------------------------------------------------------------
// Scratch (device globals; no allocations allowed)
__device__ unsigned long long g_best[MROWS];
__device__ int   g_idx[MROWS];
__device__ float g_counts[VCODES];
__device__ float g_encsum[VCODES * DDIM];
__device__ float g_wsq[VCODES];
__device__ float g_sumN;
__device__ float g_qd;
__device__ __nv_bfloat16 g_abf[MROWS * DDIM];    // flat x, bf16
__device__ __nv_bfloat16 g_wbf[VCODES * DDIM];   // weight, bf16
__device__ __nv_bfloat16 g_scores[(size_t)MROWS * VCODES];  // coarse scores

// ---------------------------------------------------------------------------
__device__ __forceinline__ uint32_t smem_u32(const void* p) {
    uint32_t a;
    asm("{ .reg .u64 t; cvta.to.shared.u64 t, %1; cvt.u32.u64 %0, t; }" : "=r"(a) : "l"(p));
    return a;
}
__device__ __forceinline__ void cp16(uint32_t dst, const void* src) {
    asm volatile("cp.async.cg.shared.global [%0], [%1], 16;" :: "r"(dst), "l"(src) : "memory");
}
__device__ __forceinline__ void ldm4(uint32_t* r, uint32_t addr) {
    asm volatile("ldmatrix.sync.aligned.m8n8.x4.shared.b16 {%0,%1,%2,%3}, [%4];"
                 : "=r"(r[0]), "=r"(r[1]), "=r"(r[2]), "=r"(r[3]) : "r"(addr));
}
__device__ __forceinline__ void mma16816(float* c, const uint32_t* a, const uint32_t* b) {
    asm volatile(
        "mma.sync.aligned.m16n8k16.row.col.f32.bf16.bf16.f32 "
        "{%0,%1,%2,%3}, {%4,%5,%6,%7}, {%8,%9}, {%0,%1,%2,%3};"
        : "+f"(c[0]), "+f"(c[1]), "+f"(c[2]), "+f"(c[3])
        : "r"(a[0]), "r"(a[1]), "r"(a[2]), "r"(a[3]), "r"(b[0]), "r"(b[1]));
}
__device__ __forceinline__ void st_cs32(void* p, uint32_t v) {
    asm volatile("st.global.cs.b32 [%0], %1;" :: "l"(p), "r"(v) : "memory");
}

// ---------------------------------------------------------------------------
__global__ void k_zero() {
    int i = blockIdx.x * 256 + threadIdx.x;       // grid covers 2097152
    if (i < VCODES * DDIM) g_encsum[i] = 0.0f;
    if (i < MROWS)  g_best[i] = 0ull;
    if (i < VCODES) g_counts[i] = 0.0f;
    if (i == 0) { g_sumN = 0.0f; g_qd = 0.0f; }
}

// x (b, D=k, s) -> g_abf[r=b*4096+s][k] bf16
__global__ void k_prep_x(const float* __restrict__ x) {
    __shared__ float t[32][33];
    int k0 = blockIdx.x * 32, s0 = blockIdx.y * 32, b = blockIdx.z;
    int tx = threadIdx.x, ty = threadIdx.y;       // (32, 8)
#pragma unroll
    for (int i = 0; i < 4; ++i)
        t[ty + i * 8][tx] = x[(size_t)b * 1048576 + (size_t)(k0 + ty + i * 8) * SPAT + s0 + tx];
    __syncthreads();
#pragma unroll
    for (int i = 0; i < 4; ++i) {
        int r = b * SPAT + s0 + ty + i * 8;
        g_abf[(size_t)r * DDIM + k0 + tx] = __float2bfloat16(t[tx][ty + i * 8]);
    }
}

// weight -> bf16; wsq per code; sum(N)
__global__ void k_prep_w(const float* __restrict__ w, const float* __restrict__ N) {
    int gid  = blockIdx.x * 256 + threadIdx.x;
    int v = gid >> 5, lane = gid & 31;
    const float* row = w + (size_t)v * DDIM;
    float s = 0.0f;
#pragma unroll
    for (int t = lane; t < DDIM; t += 32) {
        float a = row[t];
        s += a * a;
        g_wbf[(size_t)v * DDIM + t] = __float2bfloat16(a);
    }
#pragma unroll
    for (int o = 16; o; o >>= 1) s += __shfl_xor_sync(0xFFFFFFFFu, s, o);
    if (lane == 0) {
        g_wsq[v] = s;
        atomicAdd(&g_sumN, N[v]);
    }
}

// ---------------------------------------------------------------------------
// bf16 mma.sync GEMM: C[128m x 128n] per CTA, 3-stage cp.async pipeline,
// 64B rows with XOR swizzle, main loop FULLY UNROLLED (stage idx = immediates).
__global__ __launch_bounds__(256, 2) void k_gemm() {
    __shared__ __align__(16) char sm[49152];
    const int tid = threadIdx.x;
    const int lane = tid & 31, wid = tid >> 5;
    const int wm = wid & 1, wn = wid >> 1;        // warp tile 64m x 32n
    const int jbase = blockIdx.x * 128;
    const int rbase = blockIdx.y * 128;
    const uint32_t smb = smem_u32(sm);

    const int sel = lane >> 3, rin = lane & 7;

    // ldmatrix fragment offsets (per kstep, XOR-swizzled)
    uint32_t offA[4][2], offB[2][2];
#pragma unroll
    for (int i = 0; i < 4; ++i) {
        int row = wm * 64 + i * 16 + rin + ((sel & 1) << 3);
        int h = sel >> 1, v = (row >> 1) & 3;
#pragma unroll
        for (int ks = 0; ks < 2; ++ks)
            offA[i][ks] = (uint32_t)(row * 64 + (((ks * 2 + h) ^ v) << 4));
    }
#pragma unroll
    for (int p = 0; p < 2; ++p) {
        int row = wn * 32 + p * 16 + rin + ((sel >> 1) << 3);
        int h = sel & 1, v = (row >> 1) & 3;
#pragma unroll
        for (int ks = 0; ks < 2; ++ks)
            offB[p][ks] = (uint32_t)(8192 + row * 64 + (((ks * 2 + h) ^ v) << 4));
    }

    // cp.async store offsets / source pointers
    const int rw = tid >> 2, cc = tid & 3;
    const uint32_t dA0 = (uint32_t)(rw * 64 + ((cc ^ ((rw >> 1) & 3)) << 4));
    const uint32_t dA1 = (uint32_t)((rw + 64) * 64 + ((cc ^ (((rw + 64) >> 1) & 3)) << 4));
    const uint32_t dB0 = 8192 + dA0;
    const uint32_t dB1 = 8192 + dA1;
    const __nv_bfloat16* sA0 = g_abf + (size_t)(rbase + rw) * DDIM + cc * 8;
    const __nv_bfloat16* sA1 = sA0 + (size_t)64 * DDIM;
    const __nv_bfloat16* sB0 = g_wbf + (size_t)(jbase + rw) * DDIM + cc * 8;
    const __nv_bfloat16* sB1 = sB0 + (size_t)64 * DDIM;

    float acc[4][4][4];
#pragma unroll
    for (int i = 0; i < 4; ++i)
#pragma unroll
        for (int j = 0; j < 4; ++j)
#pragma unroll
            for (int q = 0; q < 4; ++q) acc[i][j][q] = 0.0f;

#define LOAD_STAGE(st, ko)                                                \
    do {                                                                  \
        uint32_t sb_ = smb + (st) * 16384;                                \
        cp16(sb_ + dA0, sA0 + (ko)); cp16(sb_ + dA1, sA1 + (ko));         \
        cp16(sb_ + dB0, sB0 + (ko)); cp16(sb_ + dB1, sB1 + (ko));         \
        asm volatile("cp.async.commit_group;" ::: "memory");              \
    } while (0)

    LOAD_STAGE(0, 0);
    LOAD_STAGE(1, 32);

#pragma unroll
    for (int c = 0; c < 8; ++c) {
        if (c < 7) asm volatile("cp.async.wait_group 1;" ::: "memory");
        else       asm volatile("cp.async.wait_group 0;" ::: "memory");
        __syncthreads();
        if (c < 6) LOAD_STAGE((c + 2) % 3, (c + 2) * 32);
        uint32_t sb = smb + (c % 3) * 16384;
#pragma unroll
        for (int ks = 0; ks < 2; ++ks) {
            uint32_t a[4][4], bf[4][2];
#pragma unroll
            for (int i = 0; i < 4; ++i) ldm4(a[i], sb + offA[i][ks]);
#pragma unroll
            for (int p = 0; p < 2; ++p) {
                uint32_t r4[4];
                ldm4(r4, sb + offB[p][ks]);
                bf[2 * p][0] = r4[0]; bf[2 * p][1] = r4[1];
                bf[2 * p + 1][0] = r4[2]; bf[2 * p + 1][1] = r4[3];
            }
#pragma unroll
            for (int i = 0; i < 4; ++i)
#pragma unroll
                for (int j = 0; j < 4; ++j)
                    mma16816(acc[i][j], a[i], bf[j]);
        }
    }
#undef LOAD_STAGE

    // epilogue: scores = acc - 0.5*wsq; store bf16 (streaming); per-row argmax
    const int lq = lane >> 2, lr = lane & 3;
    float bv[8]; int bj[8];
#pragma unroll
    for (int s = 0; s < 8; ++s) { bv[s] = -3.4e38f; bj[s] = 0; }

#pragma unroll
    for (int j = 0; j < 4; ++j) {
        int col = jbase + wn * 32 + j * 8 + lr * 2;
        float2 wq = *reinterpret_cast<const float2*>(&g_wsq[col]);
#pragma unroll
        for (int i = 0; i < 4; ++i) {
#pragma unroll
            for (int h = 0; h < 2; ++h) {
                float s0 = acc[i][j][h * 2 + 0] - 0.5f * wq.x;
                float s1 = acc[i][j][h * 2 + 1] - 0.5f * wq.y;
                int grow = rbase + wm * 64 + i * 16 + lq + h * 8;
                __nv_bfloat162 pr = __floats2bfloat162_rn(s0, s1);
                st_cs32(&g_scores[(size_t)grow * VCODES + col],
                        *reinterpret_cast<uint32_t*>(&pr));
                int slot = i * 2 + h;
                if (s0 > bv[slot]) { bv[slot] = s0; bj[slot] = col; }
                if (s1 > bv[slot]) { bv[slot] = s1; bj[slot] = col + 1; }
            }
        }
    }
#pragma unroll
    for (int s = 0; s < 8; ++s) {
        unsigned u = __float_as_uint(bv[s]);
        u = (u & 0x80000000u) ? ~u : (u | 0x80000000u);
        unsigned long long key = ((unsigned long long)u << 32) |
                                 (unsigned)(0xFFFFFFFFu - (unsigned)bj[s]);
#pragma unroll
        for (int o = 1; o < 4; o <<= 1) {
            unsigned long long v = __shfl_xor_sync(0xFFFFFFFFu, key, o);
            if (v > key) key = v;
        }
        if (lr == 0) {
            int grow = rbase + wm * 64 + (s >> 1) * 16 + lq + (s & 1) * 8;
            atomicMax(&g_best[grow], key);
        }
    }
}

// ---------------------------------------------------------------------------
// Repair: per-row warp rescans bf16 scores (streaming loads), exact fp32
// recompute of candidates within MARGIN of the coarse winner.
__global__ void k_repair(const float* __restrict__ x, const float* __restrict__ w,
                         float* __restrict__ out) {
    int r = blockIdx.x * 8 + (threadIdx.x >> 5);
    int lane = threadIdx.x & 31;
    unsigned long long kk = g_best[r];
    unsigned u = (unsigned)(kk >> 32);
    unsigned bits = (u & 0x80000000u) ? (u & 0x7FFFFFFFu) : ~u;
    float thr = __uint_as_float(bits) - MARGIN;
    int b = r >> 12, s = r & 4095;
    const float* xb = x + (size_t)b * 1048576 + s;
    float bestv = -3.4e38f;
    int   bestj = 0;
    const uint4* rowp = reinterpret_cast<const uint4*>(g_scores + (size_t)r * VCODES);
#pragma unroll 1
    for (int it = 0; it < 32; ++it) {
        uint4 v = __ldcs(rowp + it * 32 + lane);
        unsigned m = 0;
        unsigned wds[4] = {v.x, v.y, v.z, v.w};
#pragma unroll
        for (int q = 0; q < 4; ++q) {
            __nv_bfloat162 h2 = *reinterpret_cast<__nv_bfloat162*>(&wds[q]);
            float2 f = __bfloat1622float2(h2);
            if (f.x >= thr) m |= 1u << (2 * q);
            if (f.y >= thr) m |= 1u << (2 * q + 1);
        }
        unsigned act = __ballot_sync(0xFFFFFFFFu, m != 0);
        while (act) {
            int src = __ffs(act) - 1; act &= act - 1;
            unsigned mm = __shfl_sync(0xFFFFFFFFu, m, src);
            while (mm) {
                int bit = __ffs(mm) - 1; mm &= mm - 1;
                int j = it * 256 + src * 8 + bit;
                const float* wr = w + (size_t)j * DDIM;
                float p = 0.0f;
#pragma unroll
                for (int q = 0; q < 8; ++q) {
                    int k = lane + q * 32;
                    p += xb[(size_t)k * SPAT] * wr[k];
                }
#pragma unroll
                for (int o = 16; o; o >>= 1) p += __shfl_xor_sync(0xFFFFFFFFu, p, o);
                float sc = p - 0.5f * g_wsq[j];
                if (sc > bestv) { bestv = sc; bestj = j; }   // ascending j -> first-idx tie-break
            }
        }
    }
    if (lane == 0) {
        g_idx[r] = bestj;
        out[O_IDX + r] = (float)bestj;
        atomicAdd(&g_counts[bestj], 1.0f);
    }
}

// ---------------------------------------------------------------------------
// quant write (coalesced over spatial), enc_sum atomics, quant_diff
__global__ void k_assign(const float* __restrict__ x, const float* __restrict__ w,
                         float* __restrict__ out) {
    __shared__ int sidx[128];
    __shared__ float red[8];
    int bi = blockIdx.x;
    int b = bi >> 5, s0 = (bi & 31) * 128;
    int tid = threadIdx.x, ts = tid & 127, dg = tid >> 7;
    if (tid < 128) sidx[tid] = g_idx[b * SPAT + s0 + tid];
    __syncthreads();
    int j = sidx[ts];
    const float* wr = w + (size_t)j * DDIM;
    float* er = g_encsum + (size_t)j * DDIM;
    size_t basex = (size_t)b * 1048576 + s0 + ts;
    float qd = 0.0f;
#pragma unroll 4
    for (int d = dg; d < 256; d += 2) {
        size_t off = basex + (size_t)d * SPAT;
        float xv = x[off];
        float wv = __ldg(wr + d);
        out[O_QUANT + off] = (wv - xv) + xv;
        float df = xv - wv;
        qd += df * df;
        atomicAdd(er + d, xv);
    }
#pragma unroll
    for (int o = 16; o; o >>= 1) qd += __shfl_xor_sync(0xFFFFFFFFu, qd, o);
    if ((tid & 31) == 0) red[tid >> 5] = qd;
    __syncthreads();
    if (tid == 0) {
        float t = 0.0f;
#pragma unroll
        for (int i = 0; i < 8; ++i) t += red[i];
        atomicAdd(&g_qd, t);
    }
}

// ---------------------------------------------------------------------------
__global__ void k_update(const float* __restrict__ N, const float* __restrict__ z_avg,
                         float* __restrict__ out) {
    int i = blockIdx.x * 256 + threadIdx.x;
    if (i >= VCODES * DDIM) return;
    int v = i >> 8, d = i & 255;
    float gamma = 0.99f, om = 0.01f, eps = 1e-7f;
    float n  = gamma * g_sumN + om * (float)MROWS;
    float nN = gamma * N[v] + om * g_counts[v];
    float wgt = (nN + eps) / (n + (float)VCODES * eps) * n;
    float za = gamma * z_avg[i] + om * g_encsum[i];
    out[O_ZAVG + i] = za;
    out[O_NEWW + i] = za / wgt;
    if (d == 0) out[O_NEWN + v] = nN;
    if (i == 0) out[O_QD] = g_qd * (1.0f / 8388608.0f);
}

// ---------------------------------------------------------------------------
extern "C" void kernel_launch(void* const* d_in, const int* in_sizes, int n_in,
                              void* d_out, int out_size) {
    const float* x    = (const float*)d_in[0];
    const float* w    = (const float*)d_in[1];
    const float* N    = (const float*)d_in[2];
    const float* zavg = (const float*)d_in[3];
    float* out = (float*)d_out;

    k_zero<<<8192, 256>>>();
    k_prep_x<<<dim3(8, 128, 8), dim3(32, 8)>>>(x);
    k_prep_w<<<1024, 256>>>(w, N);
    k_gemm<<<dim3(VCODES / 128, MROWS / 128), 256>>>();
    k_repair<<<MROWS / 8, 256>>>(x, w, out);
    k_assign<<<256, 256>>>(x, w, out);
    k_update<<<VCODES * DDIM / 256, 256>>>(N, zavg, out);
}

// round 7
// speedup vs baseline: 3.4717x; 1.0033x over previous
#include <cuda_runtime.h>
#include <cuda_bf16.h>
#include <cstdint>

// Problem constants
#define VCODES 8192
#define DDIM   256
#define MROWS  32768      // 8 * 16*16*16
#define SPAT   4096       // 16*16*16

// Output layout (concatenated f32)
#define O_QUANT 0ul
#define O_IDX   8388608ul
#define O_QD    8421376ul
#define O_NEWN  8421377ul
#define O_ZAVG  8429569ul
#define O_NEWW  10526721ul

#define MARGIN 3.0f

// ---------------------------------------------------------------------------
// Scratch (device globals; no allocations allowed)
__device__ unsigned long long g_best[MROWS];
__device__ int   g_idx[MROWS];
__device__ float g_counts[VCODES];
__device__ float g_encsum[VCODES * DDIM];
__device__ float g_wsq[VCODES];
__device__ float g_sumN;
__device__ float g_qd;
__device__ __nv_bfloat16 g_abf[MROWS * DDIM];    // flat x, bf16
__device__ __nv_bfloat16 g_wbf[VCODES * DDIM];   // weight, bf16
__device__ __nv_bfloat16 g_scores[(size_t)MROWS * VCODES];  // coarse scores

// ---------------------------------------------------------------------------
__device__ __forceinline__ uint32_t smem_u32(const void* p) {
    uint32_t a;
    asm("{ .reg .u64 t; cvta.to.shared.u64 t, %1; cvt.u32.u64 %0, t; }" : "=r"(a) : "l"(p));
    return a;
}
__device__ __forceinline__ void cp16(uint32_t dst, const void* src) {
    asm volatile("cp.async.cg.shared.global [%0], [%1], 16;" :: "r"(dst), "l"(src) : "memory");
}
__device__ __forceinline__ void ldm4(uint32_t* r, uint32_t addr) {
    asm volatile("ldmatrix.sync.aligned.m8n8.x4.shared.b16 {%0,%1,%2,%3}, [%4];"
                 : "=r"(r[0]), "=r"(r[1]), "=r"(r[2]), "=r"(r[3]) : "r"(addr));
}
__device__ __forceinline__ void mma16816(float* c, const uint32_t* a, const uint32_t* b) {
    asm volatile(
        "mma.sync.aligned.m16n8k16.row.col.f32.bf16.bf16.f32 "
        "{%0,%1,%2,%3}, {%4,%5,%6,%7}, {%8,%9}, {%0,%1,%2,%3};"
        : "+f"(c[0]), "+f"(c[1]), "+f"(c[2]), "+f"(c[3])
        : "r"(a[0]), "r"(a[1]), "r"(a[2]), "r"(a[3]), "r"(b[0]), "r"(b[1]));
}
__device__ __forceinline__ void st_cs32(void* p, uint32_t v) {
    asm volatile("st.global.cs.b32 [%0], %1;" :: "l"(p), "r"(v) : "memory");
}

// ---------------------------------------------------------------------------
__global__ void k_zero() {
    int i = blockIdx.x * 256 + threadIdx.x;       // grid covers 2097152
    if (i < VCODES * DDIM) g_encsum[i] = 0.0f;
    if (i < MROWS)  g_best[i] = 0ull;
    if (i < VCODES) g_counts[i] = 0.0f;
    if (i == 0) { g_sumN = 0.0f; g_qd = 0.0f; }
}

// x (b, D=k, s) -> g_abf[r=b*4096+s][k] bf16
__global__ void k_prep_x(const float* __restrict__ x) {
    __shared__ float t[32][33];
    int k0 = blockIdx.x * 32, s0 = blockIdx.y * 32, b = blockIdx.z;
    int tx = threadIdx.x, ty = threadIdx.y;       // (32, 8)
#pragma unroll
    for (int i = 0; i < 4; ++i)
        t[ty + i * 8][tx] = x[(size_t)b * 1048576 + (size_t)(k0 + ty + i * 8) * SPAT + s0 + tx];
    __syncthreads();
#pragma unroll
    for (int i = 0; i < 4; ++i) {
        int r = b * SPAT + s0 + ty + i * 8;
        g_abf[(size_t)r * DDIM + k0 + tx] = __float2bfloat16(t[tx][ty + i * 8]);
    }
}

// weight -> bf16; wsq per code; sum(N)
__global__ void k_prep_w(const float* __restrict__ w, const float* __restrict__ N) {
    int gid  = blockIdx.x * 256 + threadIdx.x;
    int v = gid >> 5, lane = gid & 31;
    const float* row = w + (size_t)v * DDIM;
    float s = 0.0f;
#pragma unroll
    for (int t = lane; t < DDIM; t += 32) {
        float a = row[t];
        s += a * a;
        g_wbf[(size_t)v * DDIM + t] = __float2bfloat16(a);
    }
#pragma unroll
    for (int o = 16; o; o >>= 1) s += __shfl_xor_sync(0xFFFFFFFFu, s, o);
    if (lane == 0) {
        g_wsq[v] = s;
        atomicAdd(&g_sumN, N[v]);
    }
}

// ---------------------------------------------------------------------------
// bf16 mma.sync GEMM: CTA 128x128, 4 warps of 64x64 (2x less LDSM dup),
// 3-stage cp.async pipeline, 64B rows with XOR swizzle, fully unrolled.
__global__ __launch_bounds__(128, 2) void k_gemm() {
    __shared__ __align__(16) char sm[49152];
    const int tid = threadIdx.x;
    const int lane = tid & 31, wid = tid >> 5;
    const int wm = wid & 1, wn = wid >> 1;        // 2x2 warps, 64m x 64n each
    const int jbase = blockIdx.x * 128;
    const int rbase = blockIdx.y * 128;
    const uint32_t smb = smem_u32(sm);

    const int sel = lane >> 3, rin = lane & 7;

    // ldmatrix fragment offsets (per kstep, XOR-swizzled)
    uint32_t offA[4][2], offB[4][2];
#pragma unroll
    for (int i = 0; i < 4; ++i) {
        int row = wm * 64 + i * 16 + rin + ((sel & 1) << 3);
        int h = sel >> 1, v = (row >> 1) & 3;
#pragma unroll
        for (int ks = 0; ks < 2; ++ks)
            offA[i][ks] = (uint32_t)(row * 64 + (((ks * 2 + h) ^ v) << 4));
    }
#pragma unroll
    for (int p = 0; p < 4; ++p) {
        int row = wn * 64 + p * 16 + rin + ((sel >> 1) << 3);
        int h = sel & 1, v = (row >> 1) & 3;
#pragma unroll
        for (int ks = 0; ks < 2; ++ks)
            offB[p][ks] = (uint32_t)(8192 + row * 64 + (((ks * 2 + h) ^ v) << 4));
    }

    // cp.async: 8 transfers/thread covering A(128x64B) + B(128x64B)
    const __nv_bfloat16* sp[8];
    uint32_t doff[8];
#pragma unroll
    for (int e = 0; e < 8; ++e) {
        int idx = tid + e * 128;            // 0..1023
        int row = idx >> 2, cc = idx & 3;
        if (row < 128) {
            sp[e] = g_abf + (size_t)(rbase + row) * DDIM + cc * 8;
            doff[e] = (uint32_t)(row * 64 + ((cc ^ ((row >> 1) & 3)) << 4));
        } else {
            int rb = row - 128;
            sp[e] = g_wbf + (size_t)(jbase + rb) * DDIM + cc * 8;
            doff[e] = (uint32_t)(8192 + rb * 64 + ((cc ^ ((rb >> 1) & 3)) << 4));
        }
    }

    float acc[4][8][4];
#pragma unroll
    for (int i = 0; i < 4; ++i)
#pragma unroll
        for (int j = 0; j < 8; ++j)
#pragma unroll
            for (int q = 0; q < 4; ++q) acc[i][j][q] = 0.0f;

#define LOAD_STAGE(st, ko)                                                \
    do {                                                                  \
        uint32_t sb_ = smb + (st) * 16384;                                \
        _Pragma("unroll")                                                 \
        for (int e = 0; e < 8; ++e) cp16(sb_ + doff[e], sp[e] + (ko));    \
        asm volatile("cp.async.commit_group;" ::: "memory");              \
    } while (0)

    LOAD_STAGE(0, 0);
    LOAD_STAGE(1, 32);

#pragma unroll
    for (int c = 0; c < 8; ++c) {
        if (c < 7) asm volatile("cp.async.wait_group 1;" ::: "memory");
        else       asm volatile("cp.async.wait_group 0;" ::: "memory");
        __syncthreads();
        if (c < 6) LOAD_STAGE((c + 2) % 3, (c + 2) * 32);
        uint32_t sb = smb + (c % 3) * 16384;
#pragma unroll
        for (int ks = 0; ks < 2; ++ks) {
            uint32_t a[4][4], bf[8][2];
#pragma unroll
            for (int i = 0; i < 4; ++i) ldm4(a[i], sb + offA[i][ks]);
#pragma unroll
            for (int p = 0; p < 4; ++p) {
                uint32_t r4[4];
                ldm4(r4, sb + offB[p][ks]);
                bf[2 * p][0] = r4[0]; bf[2 * p][1] = r4[1];
                bf[2 * p + 1][0] = r4[2]; bf[2 * p + 1][1] = r4[3];
            }
#pragma unroll
            for (int i = 0; i < 4; ++i)
#pragma unroll
                for (int j = 0; j < 8; ++j)
                    mma16816(acc[i][j], a[i], bf[j]);
        }
    }
#undef LOAD_STAGE

    // epilogue: scores = acc - 0.5*wsq; store bf16 (streaming); per-row argmax
    const int lq = lane >> 2, lr = lane & 3;
    float bv[8]; int bj[8];
#pragma unroll
    for (int s = 0; s < 8; ++s) { bv[s] = -3.4e38f; bj[s] = 0; }

#pragma unroll
    for (int j = 0; j < 8; ++j) {
        int col = jbase + wn * 64 + j * 8 + lr * 2;
        float2 wq = *reinterpret_cast<const float2*>(&g_wsq[col]);
#pragma unroll
        for (int i = 0; i < 4; ++i) {
#pragma unroll
            for (int h = 0; h < 2; ++h) {
                float s0 = acc[i][j][h * 2 + 0] - 0.5f * wq.x;
                float s1 = acc[i][j][h * 2 + 1] - 0.5f * wq.y;
                int grow = rbase + wm * 64 + i * 16 + lq + h * 8;
                __nv_bfloat162 pr = __floats2bfloat162_rn(s0, s1);
                st_cs32(&g_scores[(size_t)grow * VCODES + col],
                        *reinterpret_cast<uint32_t*>(&pr));
                int slot = i * 2 + h;
                if (s0 > bv[slot]) { bv[slot] = s0; bj[slot] = col; }
                if (s1 > bv[slot]) { bv[slot] = s1; bj[slot] = col + 1; }
            }
        }
    }
#pragma unroll
    for (int s = 0; s < 8; ++s) {
        unsigned u = __float_as_uint(bv[s]);
        u = (u & 0x80000000u) ? ~u : (u | 0x80000000u);
        unsigned long long key = ((unsigned long long)u << 32) |
                                 (unsigned)(0xFFFFFFFFu - (unsigned)bj[s]);
#pragma unroll
        for (int o = 1; o < 4; o <<= 1) {
            unsigned long long v = __shfl_xor_sync(0xFFFFFFFFu, key, o);
            if (v > key) key = v;
        }
        if (lr == 0) {
            int grow = rbase + wm * 64 + (s >> 1) * 16 + lq + (s & 1) * 8;
            atomicMax(&g_best[grow], key);
        }
    }
}

// ---------------------------------------------------------------------------
// Repair: per-row warp rescans bf16 scores (streaming loads), exact fp32
// recompute of candidates within MARGIN of the coarse winner.
__global__ void k_repair(const float* __restrict__ x, const float* __restrict__ w,
                         float* __restrict__ out) {
    int r = blockIdx.x * 8 + (threadIdx.x >> 5);
    int lane = threadIdx.x & 31;
    unsigned long long kk = g_best[r];
    unsigned u = (unsigned)(kk >> 32);
    unsigned bits = (u & 0x80000000u) ? (u & 0x7FFFFFFFu) : ~u;
    float thr = __uint_as_float(bits) - MARGIN;
    int b = r >> 12, s = r & 4095;
    const float* xb = x + (size_t)b * 1048576 + s;
    float bestv = -3.4e38f;
    int   bestj = 0;
    const uint4* rowp = reinterpret_cast<const uint4*>(g_scores + (size_t)r * VCODES);
#pragma unroll 1
    for (int it = 0; it < 32; ++it) {
        uint4 v = __ldcs(rowp + it * 32 + lane);
        unsigned m = 0;
        unsigned wds[4] = {v.x, v.y, v.z, v.w};
#pragma unroll
        for (int q = 0; q < 4; ++q) {
            __nv_bfloat162 h2 = *reinterpret_cast<__nv_bfloat162*>(&wds[q]);
            float2 f = __bfloat1622float2(h2);
            if (f.x >= thr) m |= 1u << (2 * q);
            if (f.y >= thr) m |= 1u << (2 * q + 1);
        }
        unsigned act = __ballot_sync(0xFFFFFFFFu, m != 0);
        while (act) {
            int src = __ffs(act) - 1; act &= act - 1;
            unsigned mm = __shfl_sync(0xFFFFFFFFu, m, src);
            while (mm) {
                int bit = __ffs(mm) - 1; mm &= mm - 1;
                int j = it * 256 + src * 8 + bit;
                const float* wr = w + (size_t)j * DDIM;
                float p = 0.0f;
#pragma unroll
                for (int q = 0; q < 8; ++q) {
                    int k = lane + q * 32;
                    p += xb[(size_t)k * SPAT] * wr[k];
                }
#pragma unroll
                for (int o = 16; o; o >>= 1) p += __shfl_xor_sync(0xFFFFFFFFu, p, o);
                float sc = p - 0.5f * g_wsq[j];
                if (sc > bestv) { bestv = sc; bestj = j; }   // ascending j -> first-idx tie-break
            }
        }
    }
    if (lane == 0) {
        g_idx[r] = bestj;
        out[O_IDX + r] = (float)bestj;
        atomicAdd(&g_counts[bestj], 1.0f);
    }
}

// ---------------------------------------------------------------------------
// quant write (coalesced over spatial), enc_sum atomics, quant_diff
__global__ void k_assign(const float* __restrict__ x, const float* __restrict__ w,
                         float* __restrict__ out) {
    __shared__ int sidx[128];
    __shared__ float red[8];
    int bi = blockIdx.x;
    int b = bi >> 5, s0 = (bi & 31) * 128;
    int tid = threadIdx.x, ts = tid & 127, dg = tid >> 7;
    if (tid < 128) sidx[tid] = g_idx[b * SPAT + s0 + tid];
    __syncthreads();
    int j = sidx[ts];
    const float* wr = w + (size_t)j * DDIM;
    float* er = g_encsum + (size_t)j * DDIM;
    size_t basex = (size_t)b * 1048576 + s0 + ts;
    float qd = 0.0f;
#pragma unroll 4
    for (int d = dg; d < 256; d += 2) {
        size_t off = basex + (size_t)d * SPAT;
        float xv = x[off];
        float wv = __ldg(wr + d);
        out[O_QUANT + off] = (wv - xv) + xv;
        float df = xv - wv;
        qd += df * df;
        atomicAdd(er + d, xv);
    }
#pragma unroll
    for (int o = 16; o; o >>= 1) qd += __shfl_xor_sync(0xFFFFFFFFu, qd, o);
    if ((tid & 31) == 0) red[tid >> 5] = qd;
    __syncthreads();
    if (tid == 0) {
        float t = 0.0f;
#pragma unroll
        for (int i = 0; i < 8; ++i) t += red[i];
        atomicAdd(&g_qd, t);
    }
}

// ---------------------------------------------------------------------------
__global__ void k_update(const float* __restrict__ N, const float* __restrict__ z_avg,
                         float* __restrict__ out) {
    int i = blockIdx.x * 256 + threadIdx.x;
    if (i >= VCODES * DDIM) return;
    int v = i >> 8, d = i & 255;
    float gamma = 0.99f, om = 0.01f, eps = 1e-7f;
    float n  = gamma * g_sumN + om * (float)MROWS;
    float nN = gamma * N[v] + om * g_counts[v];
    float wgt = (nN + eps) / (n + (float)VCODES * eps) * n;
    float za = gamma * z_avg[i] + om * g_encsum[i];
    out[O_ZAVG + i] = za;
    out[O_NEWW + i] = za / wgt;
    if (d == 0) out[O_NEWN + v] = nN;
    if (i == 0) out[O_QD] = g_qd * (1.0f / 8388608.0f);
}

// ---------------------------------------------------------------------------
extern "C" void kernel_launch(void* const* d_in, const int* in_sizes, int n_in,
                              void* d_out, int out_size) {
    const float* x    = (const float*)d_in[0];
    const float* w    = (const float*)d_in[1];
    const float* N    = (const float*)d_in[2];
    const float* zavg = (const float*)d_in[3];
    float* out = (float*)d_out;

    k_zero<<<8192, 256>>>();
    k_prep_x<<<dim3(8, 128, 8), dim3(32, 8)>>>(x);
    k_prep_w<<<1024, 256>>>(w, N);
    k_gemm<<<dim3(VCODES / 128, MROWS / 128), 128>>>();
    k_repair<<<MROWS / 8, 256>>>(x, w, out);
    k_assign<<<256, 256>>>(x, w, out);
    k_update<<<VCODES * DDIM / 256, 256>>>(N, zavg, out);
}

// round 8
// speedup vs baseline: 3.4908x; 1.0055x over previous
#include <cuda_runtime.h>
#include <cuda_bf16.h>
#include <cstdint>

// Problem constants
#define VCODES 8192
#define DDIM   256
#define MROWS  32768      // 8 * 16*16*16
#define SPAT   4096       // 16*16*16

// Output layout (concatenated f32)
#define O_QUANT 0ul
#define O_IDX   8388608ul
#define O_QD    8421376ul
#define O_NEWN  8421377ul
#define O_ZAVG  8429569ul
#define O_NEWW  10526721ul

#define MARGIN 3.0f

// ---------------------------------------------------------------------------
// Scratch (device globals; no allocations allowed)
__device__ unsigned long long g_best[MROWS];
__device__ int   g_idx[MROWS];
__device__ float g_counts[VCODES];
__device__ float g_encsum[VCODES * DDIM];
__device__ float g_wsq[VCODES];
__device__ float g_sumN;
__device__ float g_qd;
__device__ __nv_bfloat16 g_abf[MROWS * DDIM];    // flat x, bf16
__device__ __nv_bfloat16 g_wbf[VCODES * DDIM];   // weight, bf16
__device__ __nv_bfloat16 g_scores[(size_t)MROWS * VCODES];  // coarse scores

// ---------------------------------------------------------------------------
__device__ __forceinline__ uint32_t smem_u32(const void* p) {
    uint32_t a;
    asm("{ .reg .u64 t; cvta.to.shared.u64 t, %1; cvt.u32.u64 %0, t; }" : "=r"(a) : "l"(p));
    return a;
}
__device__ __forceinline__ void cp16(uint32_t dst, const void* src) {
    asm volatile("cp.async.cg.shared.global [%0], [%1], 16;" :: "r"(dst), "l"(src) : "memory");
}
__device__ __forceinline__ void ldm4(uint32_t* r, uint32_t addr) {
    asm volatile("ldmatrix.sync.aligned.m8n8.x4.shared.b16 {%0,%1,%2,%3}, [%4];"
                 : "=r"(r[0]), "=r"(r[1]), "=r"(r[2]), "=r"(r[3]) : "r"(addr));
}
__device__ __forceinline__ void mma16816(float* c, const uint32_t* a, const uint32_t* b) {
    asm volatile(
        "mma.sync.aligned.m16n8k16.row.col.f32.bf16.bf16.f32 "
        "{%0,%1,%2,%3}, {%4,%5,%6,%7}, {%8,%9}, {%0,%1,%2,%3};"
        : "+f"(c[0]), "+f"(c[1]), "+f"(c[2]), "+f"(c[3])
        : "r"(a[0]), "r"(a[1]), "r"(a[2]), "r"(a[3]), "r"(b[0]), "r"(b[1]));
}
__device__ __forceinline__ void st_cs32(void* p, uint32_t v) {
    asm volatile("st.global.cs.b32 [%0], %1;" :: "l"(p), "r"(v) : "memory");
}

// ---------------------------------------------------------------------------
__global__ void k_zero() {
    int i = blockIdx.x * 256 + threadIdx.x;       // grid covers 2097152
    if (i < VCODES * DDIM) g_encsum[i] = 0.0f;
    if (i < MROWS)  g_best[i] = 0ull;
    if (i < VCODES) g_counts[i] = 0.0f;
    if (i == 0) { g_sumN = 0.0f; g_qd = 0.0f; }
}

// x (b, D=k, s) -> g_abf[r=b*4096+s][k] bf16
__global__ void k_prep_x(const float* __restrict__ x) {
    __shared__ float t[32][33];
    int k0 = blockIdx.x * 32, s0 = blockIdx.y * 32, b = blockIdx.z;
    int tx = threadIdx.x, ty = threadIdx.y;       // (32, 8)
#pragma unroll
    for (int i = 0; i < 4; ++i)
        t[ty + i * 8][tx] = x[(size_t)b * 1048576 + (size_t)(k0 + ty + i * 8) * SPAT + s0 + tx];
    __syncthreads();
#pragma unroll
    for (int i = 0; i < 4; ++i) {
        int r = b * SPAT + s0 + ty + i * 8;
        g_abf[(size_t)r * DDIM + k0 + tx] = __float2bfloat16(t[tx][ty + i * 8]);
    }
}

// weight -> bf16; wsq per code; sum(N)
__global__ void k_prep_w(const float* __restrict__ w, const float* __restrict__ N) {
    int gid  = blockIdx.x * 256 + threadIdx.x;
    int v = gid >> 5, lane = gid & 31;
    const float* row = w + (size_t)v * DDIM;
    float s = 0.0f;
#pragma unroll
    for (int t = lane; t < DDIM; t += 32) {
        float a = row[t];
        s += a * a;
        g_wbf[(size_t)v * DDIM + t] = __float2bfloat16(a);
    }
#pragma unroll
    for (int o = 16; o; o >>= 1) s += __shfl_xor_sync(0xFFFFFFFFu, s, o);
    if (lane == 0) {
        g_wsq[v] = s;
        atomicAdd(&g_sumN, N[v]);
    }
}

// ---------------------------------------------------------------------------
// bf16 mma.sync GEMM: CTA 128x128, 8 warps of 64x32, K-chunk=64 (4 barriers),
// 3-stage x 32KB pipeline in 96KB dynamic smem, 128B rows, c^=(row&7) swizzle.
#define STAGE_B 32768
#define SMEM_DYN (3 * STAGE_B)

__global__ __launch_bounds__(256, 2) void k_gemm() {
    extern __shared__ __align__(16) char sm[];
    const int tid = threadIdx.x;
    const int lane = tid & 31, wid = tid >> 5;
    const int wm = wid & 1, wn = wid >> 1;        // warp tile 64m x 32n
    const int jbase = blockIdx.x * 128;
    const int rbase = blockIdx.y * 128;
    const uint32_t smb = smem_u32(sm);

    const int sel = lane >> 3, rin = lane & 7;

    // fragment row bases + swizzle params (column chunk computed inline)
    uint32_t baseA[4]; int vA[4], hA;
#pragma unroll
    for (int i = 0; i < 4; ++i) {
        int row = wm * 64 + i * 16 + rin + ((sel & 1) << 3);
        baseA[i] = (uint32_t)(row * 128);
        vA[i] = row & 7;
    }
    hA = sel >> 1;
    uint32_t baseB[2]; int vB[2], hB;
#pragma unroll
    for (int p = 0; p < 2; ++p) {
        int row = wn * 32 + p * 16 + rin + ((sel >> 1) << 3);
        baseB[p] = (uint32_t)(16384 + row * 128);
        vB[p] = row & 7;
    }
    hB = sel & 1;

    // cp.async: 8 x 16B per thread per stage (A: e 0..3, B: e 4..7)
    const __nv_bfloat16* sp[8];
    uint32_t doff[8];
#pragma unroll
    for (int e = 0; e < 8; ++e) {
        int idx = tid + (e & 3) * 256;             // 0..1023
        int row = idx >> 3, c = idx & 7;
        if (e < 4) {
            sp[e] = g_abf + (size_t)(rbase + row) * DDIM + c * 8;
            doff[e] = (uint32_t)(row * 128 + ((c ^ (row & 7)) << 4));
        } else {
            sp[e] = g_wbf + (size_t)(jbase + row) * DDIM + c * 8;
            doff[e] = (uint32_t)(16384 + row * 128 + ((c ^ (row & 7)) << 4));
        }
    }

    float acc[4][4][4];
#pragma unroll
    for (int i = 0; i < 4; ++i)
#pragma unroll
        for (int j = 0; j < 4; ++j)
#pragma unroll
            for (int q = 0; q < 4; ++q) acc[i][j][q] = 0.0f;

#define LOAD_STAGE(st, ko)                                                \
    do {                                                                  \
        uint32_t sb_ = smb + (st) * STAGE_B;                              \
        _Pragma("unroll")                                                 \
        for (int e = 0; e < 8; ++e) cp16(sb_ + doff[e], sp[e] + (ko));    \
        asm volatile("cp.async.commit_group;" ::: "memory");              \
    } while (0)

    LOAD_STAGE(0, 0);
    LOAD_STAGE(1, 64);

#pragma unroll
    for (int c = 0; c < 4; ++c) {
        if (c < 3) asm volatile("cp.async.wait_group 1;" ::: "memory");
        else       asm volatile("cp.async.wait_group 0;" ::: "memory");
        __syncthreads();
        if (c < 2) LOAD_STAGE(c + 2 - ((c + 2 >= 3) ? 3 : 0), (c + 2) * 64);
        uint32_t sb = smb + (c % 3) * STAGE_B;
#pragma unroll
        for (int ks = 0; ks < 4; ++ks) {          // 4 x K16 per chunk
            uint32_t a[4][4], bf[4][2];
#pragma unroll
            for (int i = 0; i < 4; ++i)
                ldm4(a[i], sb + baseA[i] + (((ks * 2 + hA) ^ vA[i]) << 4));
#pragma unroll
            for (int p = 0; p < 2; ++p) {
                uint32_t r4[4];
                ldm4(r4, sb + baseB[p] + (((ks * 2 + hB) ^ vB[p]) << 4));
                bf[2 * p][0] = r4[0]; bf[2 * p][1] = r4[1];
                bf[2 * p + 1][0] = r4[2]; bf[2 * p + 1][1] = r4[3];
            }
#pragma unroll
            for (int i = 0; i < 4; ++i)
#pragma unroll
                for (int j = 0; j < 4; ++j)
                    mma16816(acc[i][j], a[i], bf[j]);
        }
    }
#undef LOAD_STAGE

    // epilogue: scores = acc - 0.5*wsq; store bf16 (streaming); per-row argmax
    const int lq = lane >> 2, lr = lane & 3;
    float bv[8]; int bj[8];
#pragma unroll
    for (int s = 0; s < 8; ++s) { bv[s] = -3.4e38f; bj[s] = 0; }

#pragma unroll
    for (int j = 0; j < 4; ++j) {
        int col = jbase + wn * 32 + j * 8 + lr * 2;
        float2 wq = *reinterpret_cast<const float2*>(&g_wsq[col]);
#pragma unroll
        for (int i = 0; i < 4; ++i) {
#pragma unroll
            for (int h = 0; h < 2; ++h) {
                float s0 = acc[i][j][h * 2 + 0] - 0.5f * wq.x;
                float s1 = acc[i][j][h * 2 + 1] - 0.5f * wq.y;
                int grow = rbase + wm * 64 + i * 16 + lq + h * 8;
                __nv_bfloat162 pr = __floats2bfloat162_rn(s0, s1);
                st_cs32(&g_scores[(size_t)grow * VCODES + col],
                        *reinterpret_cast<uint32_t*>(&pr));
                int slot = i * 2 + h;
                if (s0 > bv[slot]) { bv[slot] = s0; bj[slot] = col; }
                if (s1 > bv[slot]) { bv[slot] = s1; bj[slot] = col + 1; }
            }
        }
    }
#pragma unroll
    for (int s = 0; s < 8; ++s) {
        unsigned u = __float_as_uint(bv[s]);
        u = (u & 0x80000000u) ? ~u : (u | 0x80000000u);
        unsigned long long key = ((unsigned long long)u << 32) |
                                 (unsigned)(0xFFFFFFFFu - (unsigned)bj[s]);
#pragma unroll
        for (int o = 1; o < 4; o <<= 1) {
            unsigned long long v = __shfl_xor_sync(0xFFFFFFFFu, key, o);
            if (v > key) key = v;
        }
        if (lr == 0) {
            int grow = rbase + wm * 64 + (s >> 1) * 16 + lq + (s & 1) * 8;
            atomicMax(&g_best[grow], key);
        }
    }
}

// ---------------------------------------------------------------------------
// Repair: per-row warp rescans bf16 scores (streaming loads), exact fp32
// recompute of candidates within MARGIN of the coarse winner.
__global__ void k_repair(const float* __restrict__ x, const float* __restrict__ w,
                         float* __restrict__ out) {
    int r = blockIdx.x * 8 + (threadIdx.x >> 5);
    int lane = threadIdx.x & 31;
    unsigned long long kk = g_best[r];
    unsigned u = (unsigned)(kk >> 32);
    unsigned bits = (u & 0x80000000u) ? (u & 0x7FFFFFFFu) : ~u;
    float thr = __uint_as_float(bits) - MARGIN;
    int b = r >> 12, s = r & 4095;
    const float* xb = x + (size_t)b * 1048576 + s;
    float bestv = -3.4e38f;
    int   bestj = 0;
    const uint4* rowp = reinterpret_cast<const uint4*>(g_scores + (size_t)r * VCODES);
#pragma unroll 1
    for (int it = 0; it < 32; ++it) {
        uint4 v = __ldcs(rowp + it * 32 + lane);
        unsigned m = 0;
        unsigned wds[4] = {v.x, v.y, v.z, v.w};
#pragma unroll
        for (int q = 0; q < 4; ++q) {
            __nv_bfloat162 h2 = *reinterpret_cast<__nv_bfloat162*>(&wds[q]);
            float2 f = __bfloat1622float2(h2);
            if (f.x >= thr) m |= 1u << (2 * q);
            if (f.y >= thr) m |= 1u << (2 * q + 1);
        }
        unsigned act = __ballot_sync(0xFFFFFFFFu, m != 0);
        while (act) {
            int src = __ffs(act) - 1; act &= act - 1;
            unsigned mm = __shfl_sync(0xFFFFFFFFu, m, src);
            while (mm) {
                int bit = __ffs(mm) - 1; mm &= mm - 1;
                int j = it * 256 + src * 8 + bit;
                const float* wr = w + (size_t)j * DDIM;
                float p = 0.0f;
#pragma unroll
                for (int q = 0; q < 8; ++q) {
                    int k = lane + q * 32;
                    p += xb[(size_t)k * SPAT] * wr[k];
                }
#pragma unroll
                for (int o = 16; o; o >>= 1) p += __shfl_xor_sync(0xFFFFFFFFu, p, o);
                float sc = p - 0.5f * g_wsq[j];
                if (sc > bestv) { bestv = sc; bestj = j; }   // ascending j -> first-idx tie-break
            }
        }
    }
    if (lane == 0) {
        g_idx[r] = bestj;
        out[O_IDX + r] = (float)bestj;
        atomicAdd(&g_counts[bestj], 1.0f);
    }
}

// ---------------------------------------------------------------------------
// quant write (coalesced over spatial), enc_sum atomics, quant_diff
__global__ void k_assign(const float* __restrict__ x, const float* __restrict__ w,
                         float* __restrict__ out) {
    __shared__ int sidx[128];
    __shared__ float red[8];
    int bi = blockIdx.x;
    int b = bi >> 5, s0 = (bi & 31) * 128;
    int tid = threadIdx.x, ts = tid & 127, dg = tid >> 7;
    if (tid < 128) sidx[tid] = g_idx[b * SPAT + s0 + tid];
    __syncthreads();
    int j = sidx[ts];
    const float* wr = w + (size_t)j * DDIM;
    float* er = g_encsum + (size_t)j * DDIM;
    size_t basex = (size_t)b * 1048576 + s0 + ts;
    float qd = 0.0f;
#pragma unroll 4
    for (int d = dg; d < 256; d += 2) {
        size_t off = basex + (size_t)d * SPAT;
        float xv = x[off];
        float wv = __ldg(wr + d);
        out[O_QUANT + off] = (wv - xv) + xv;
        float df = xv - wv;
        qd += df * df;
        atomicAdd(er + d, xv);
    }
#pragma unroll
    for (int o = 16; o; o >>= 1) qd += __shfl_xor_sync(0xFFFFFFFFu, qd, o);
    if ((tid & 31) == 0) red[tid >> 5] = qd;
    __syncthreads();
    if (tid == 0) {
        float t = 0.0f;
#pragma unroll
        for (int i = 0; i < 8; ++i) t += red[i];
        atomicAdd(&g_qd, t);
    }
}

// ---------------------------------------------------------------------------
__global__ void k_update(const float* __restrict__ N, const float* __restrict__ z_avg,
                         float* __restrict__ out) {
    int i = blockIdx.x * 256 + threadIdx.x;
    if (i >= VCODES * DDIM) return;
    int v = i >> 8, d = i & 255;
    float gamma = 0.99f, om = 0.01f, eps = 1e-7f;
    float n  = gamma * g_sumN + om * (float)MROWS;
    float nN = gamma * N[v] + om * g_counts[v];
    float wgt = (nN + eps) / (n + (float)VCODES * eps) * n;
    float za = gamma * z_avg[i] + om * g_encsum[i];
    out[O_ZAVG + i] = za;
    out[O_NEWW + i] = za / wgt;
    if (d == 0) out[O_NEWN + v] = nN;
    if (i == 0) out[O_QD] = g_qd * (1.0f / 8388608.0f);
}

// ---------------------------------------------------------------------------
extern "C" void kernel_launch(void* const* d_in, const int* in_sizes, int n_in,
                              void* d_out, int out_size) {
    const float* x    = (const float*)d_in[0];
    const float* w    = (const float*)d_in[1];
    const float* N    = (const float*)d_in[2];
    const float* zavg = (const float*)d_in[3];
    float* out = (float*)d_out;

    cudaFuncSetAttribute(k_gemm, cudaFuncAttributeMaxDynamicSharedMemorySize, SMEM_DYN);

    k_zero<<<8192, 256>>>();
    k_prep_x<<<dim3(8, 128, 8), dim3(32, 8)>>>(x);
    k_prep_w<<<1024, 256>>>(w, N);
    k_gemm<<<dim3(VCODES / 128, MROWS / 128), 256, SMEM_DYN>>>();
    k_repair<<<MROWS / 8, 256>>>(x, w, out);
    k_assign<<<256, 256>>>(x, w, out);
    k_update<<<VCODES * DDIM / 256, 256>>>(N, zavg, out);
}